// round 15
// baseline (speedup 1.0000x reference)
#include <cuda_runtime.h>
#include <cuda_bf16.h>
#include <cstdint>
#include <math.h>

// Causal MHA, qkv packed [B,S,3,H,D] fp32 -> out [B,S,H,D] fp32
// B=2, S=2048, H=32, D=128.
// tcgen05 bf16 SS-mode flash attention, 3-term bf16x2 split (hh+hl+lh).
// R15 = R14 (464us, double-buffered K/V, zero same-iteration waits) +
//   (1) V convert vectorized: float4 LDGs (4x fewer loads, MLP=8)
//   (2) V convert split across ALL 256 threads: S-warps convert their
//       tid-slice after softmax (their existing MBPV wait already guards
//       Vbuf[tt&1]); C-warps convert theirs after the same wait.
//   Balances per-thread instruction load: C ~420, S ~420 (was C 600 / S 300).

#define SEQ    2048
#define HEADS  32
#define DH     128
#define BM     128
#define BN     64
#define THREADS 256

// smem byte offsets (tiles 1024-aligned for SW128 descriptors)
#define SM_TMEMPTR 0
#define SM_MBQK0   8        // +8 = MBQK1
#define SM_MBPV0   24       // +8 = MBPV1
#define SM_Q_HI    1024                     // 32768
#define SM_Q_LO    (SM_Q_HI + 32768)        // 32768
#define SM_K_HI    (SM_Q_LO + 32768)        // 2 bufs x 16384
#define SM_K_LO    (SM_K_HI + 32768)        // 2 bufs x 16384
#define SM_V_HI    (SM_K_LO + 32768)        // 2 bufs x 16384
#define SM_V_LO    (SM_V_HI + 32768)        // 2 bufs x 16384
#define SM_P_HI    (SM_V_LO + 32768)        // 16384
#define SM_P_LO    (SM_P_HI + 16384)        // 16384
#define SM_LS      (SM_P_LO + 16384)        // 128 fp32
#define SM_TOTAL   (SM_LS + 1024)           // 231424 bytes

// TMEM columns: O fp32 [0:128), S0 [128:192), S1 [192:256)
#define O_COL  0
#define S0_COL 128
#define TMEM_NCOLS 256

// idesc kind::f16: dtype F32@4, atype BF16@7, btype BF16@10, N/8@[17:23), M/16@[24:29)
#define IDESC_64 ((1u<<4)|(1u<<7)|(1u<<10)|(8u<<17)|(8u<<24))   // M=128, N=64

#if defined(__CUDA_ARCH_FEAT_SM103_ALL) || defined(__CUDA_ARCH_FEAT_SM100_ALL) || \
    defined(__CUDA_ARCH_SPECIFIC__) || defined(__CUDA_ARCH_FAMILY_SPECIFIC__)
#define HAS_TCGEN05 1
#else
#define HAS_TCGEN05 0
#endif

static __device__ __forceinline__ uint32_t smem_u32(const void* p) {
    uint32_t a;
    asm("{ .reg .u64 t; cvta.to.shared.u64 t, %1; cvt.u32.u64 %0, t; }" : "=r"(a) : "l"(p));
    return a;
}
static __device__ __forceinline__ float ex2(float x) {
    float y; asm("ex2.approx.ftz.f32 %0, %1;" : "=f"(y) : "f"(x)); return y;
}
static __device__ __forceinline__ void cvt_pair(float e0, float e1, uint32_t& hi, uint32_t& lo) {
    __nv_bfloat162 h = __float22bfloat162_rn(make_float2(e0, e1));
    uint32_t hb = *reinterpret_cast<uint32_t*>(&h);
    float r0 = e0 - __uint_as_float(hb << 16);
    float r1 = e1 - __uint_as_float(hb & 0xFFFF0000u);
    __nv_bfloat162 l = __float22bfloat162_rn(make_float2(r0, r1));
    hi = hb;
    lo = *reinterpret_cast<uint32_t*>(&l);
}
#define SWZ(o) ((o) ^ ((((uint32_t)(o)) >> 3) & 0x70u))

#if HAS_TCGEN05
static __device__ __forceinline__ uint32_t elect1() {
    uint32_t p;
    asm volatile("{\n\t.reg .pred p;\n\telect.sync _|p, 0xFFFFFFFF;\n\tselp.b32 %0,1,0,p;\n\t}" : "=r"(p));
    return p;
}
static __device__ __forceinline__ uint64_t desc_k(uint32_t addr) {
    return ((2ull<<61)|(1ull<<46)|(64ull<<32)|(1ull<<16)) | ((uint64_t)(addr>>4)&0x3FFF);
}
static __device__ __forceinline__ void mma_ss(uint32_t d, uint64_t a, uint64_t b, uint32_t en) {
    asm volatile("{\n\t.reg .pred p;\n\tsetp.ne.u32 p, %4, 0;\n\t"
        "tcgen05.mma.cta_group::1.kind::f16 [%0], %1, %2, %3, {%5,%5,%5,%5}, p;\n\t}"
        :: "r"(d), "l"(a), "l"(b), "r"(IDESC_64), "r"(en), "r"(0u) : "memory");
}
#define TC_LD32(r, addr) \
    asm volatile("tcgen05.ld.sync.aligned.32x32b.x32.b32 " \
        "{%0,%1,%2,%3,%4,%5,%6,%7,%8,%9,%10,%11,%12,%13,%14,%15," \
        "%16,%17,%18,%19,%20,%21,%22,%23,%24,%25,%26,%27,%28,%29,%30,%31}, [%32];" \
        : "=r"((r)[0]),"=r"((r)[1]),"=r"((r)[2]),"=r"((r)[3]),"=r"((r)[4]),"=r"((r)[5]),"=r"((r)[6]),"=r"((r)[7]), \
          "=r"((r)[8]),"=r"((r)[9]),"=r"((r)[10]),"=r"((r)[11]),"=r"((r)[12]),"=r"((r)[13]),"=r"((r)[14]),"=r"((r)[15]), \
          "=r"((r)[16]),"=r"((r)[17]),"=r"((r)[18]),"=r"((r)[19]),"=r"((r)[20]),"=r"((r)[21]),"=r"((r)[22]),"=r"((r)[23]), \
          "=r"((r)[24]),"=r"((r)[25]),"=r"((r)[26]),"=r"((r)[27]),"=r"((r)[28]),"=r"((r)[29]),"=r"((r)[30]),"=r"((r)[31]) \
        : "r"(addr))
#define TC_WAIT_LD() asm volatile("tcgen05.wait::ld.sync.aligned;" ::: "memory")
#define TC_FENCE_AFTER()  asm volatile("tcgen05.fence::after_thread_sync;" ::: "memory")
#define TC_FENCE_BEFORE() asm volatile("tcgen05.fence::before_thread_sync;" ::: "memory")
#define TC_COMMIT(mb) \
    asm volatile("tcgen05.commit.cta_group::1.mbarrier::arrive::one.shared::cluster.b64 [%0];" :: "r"(mb) : "memory")
#define MBAR_WAIT(mb, ph) do { \
    asm volatile("{\n\t.reg .pred P1;\n\t" \
        "WL_%=:\n\t" \
        "mbarrier.try_wait.parity.acquire.cta.shared::cta.b64 P1, [%0], %1, 0x989680;\n\t" \
        "@P1 bra.uni WD_%=;\n\tbra.uni WL_%=;\n\tWD_%=:\n\t}" \
        :: "r"(mb), "r"(ph) : "memory"); \
} while (0)
#define FENCE_ASYNC() asm volatile("fence.proxy.async.shared::cta;" ::: "memory")
#define SBAR() asm volatile("bar.sync 2, 128;" ::: "memory")   // S-warps only

// V^T convert, tid-slice: each thread handles 4 items (jp, d4); item = it*256+tid.
// Loads batched first (MLP=8), then converted + stored swizzled.
static __device__ __forceinline__ void convert_v_slice(
    const float* __restrict__ Vt, int tok, char* vhb, char* vlb, int tid) {
    float4 va[4], vb[4];
    #pragma unroll
    for (int it = 0; it < 4; ++it) {
        int item = it * 256 + tid;          // 0..1023
        int jp = item >> 5, d4 = item & 31;
        va[it] = *reinterpret_cast<const float4*>(Vt + (size_t)(2 * jp) * tok + d4 * 4);
        vb[it] = *reinterpret_cast<const float4*>(Vt + (size_t)(2 * jp + 1) * tok + d4 * 4);
    }
    #pragma unroll
    for (int it = 0; it < 4; ++it) {
        int item = it * 256 + tid;
        int jp = item >> 5, d4 = item & 31;
        uint32_t hi, lo;
        cvt_pair(va[it].x, vb[it].x, hi, lo);
        uint32_t off = SWZ((uint32_t)((4 * d4 + 0) * 128 + jp * 4));
        *reinterpret_cast<uint32_t*>(vhb + off) = hi;
        *reinterpret_cast<uint32_t*>(vlb + off) = lo;
        cvt_pair(va[it].y, vb[it].y, hi, lo);
        off = SWZ((uint32_t)((4 * d4 + 1) * 128 + jp * 4));
        *reinterpret_cast<uint32_t*>(vhb + off) = hi;
        *reinterpret_cast<uint32_t*>(vlb + off) = lo;
        cvt_pair(va[it].z, vb[it].z, hi, lo);
        off = SWZ((uint32_t)((4 * d4 + 2) * 128 + jp * 4));
        *reinterpret_cast<uint32_t*>(vhb + off) = hi;
        *reinterpret_cast<uint32_t*>(vlb + off) = lo;
        cvt_pair(va[it].w, vb[it].w, hi, lo);
        off = SWZ((uint32_t)((4 * d4 + 3) * 128 + jp * 4));
        *reinterpret_cast<uint32_t*>(vhb + off) = hi;
        *reinterpret_cast<uint32_t*>(vlb + off) = lo;
    }
}
#endif

__global__ __launch_bounds__(THREADS, 1) __cluster_dims__(1, 1, 1)
void fa_tc_kernel(const float* __restrict__ qkv, float* __restrict__ out) {
    const int qt = (int)gridDim.x - 1 - (int)blockIdx.x;  // heavy CTAs first
    const int h = blockIdx.y, b = blockIdx.z;
    const int tid = threadIdx.x, w = tid >> 5, lane = tid & 31;
    const int q0 = qt * BM;
    extern __shared__ char smem[];

    const int HD  = HEADS * DH;
    const int tok = 3 * HD;
    const size_t bhof = (size_t)b * SEQ * tok + (size_t)h * DH;
    const float* Qg = qkv + bhof;
    const float* Kg = qkv + bhof + HD;
    const float* Vg = qkv + bhof + 2 * HD;
    const int ntiles = 2 * (qt + 1);
    const float CSC = 0.12751744f;  // log2(e)/sqrt(128)

#if HAS_TCGEN05
    const uint32_t sb = smem_u32(smem);
    float* Ls = reinterpret_cast<float*>(smem + SM_LS);
    const bool cw = (w >= 4);           // C-warps 4-7
    const int  ct = tid - 128;          // C-thread index 0..127

    if (w == 0) {
        asm volatile("tcgen05.alloc.cta_group::1.sync.aligned.shared::cta.b32 [%0], %1;"
                     :: "r"(sb + SM_TMEMPTR), "r"((uint32_t)TMEM_NCOLS) : "memory");
    }
    if (tid == 0) {
        asm volatile("mbarrier.init.shared.b64 [%0], %1;" :: "r"(sb + SM_MBQK0),     "r"(1u) : "memory");
        asm volatile("mbarrier.init.shared.b64 [%0], %1;" :: "r"(sb + SM_MBQK0 + 8), "r"(1u) : "memory");
        asm volatile("mbarrier.init.shared.b64 [%0], %1;" :: "r"(sb + SM_MBPV0),     "r"(1u) : "memory");
        asm volatile("mbarrier.init.shared.b64 [%0], %1;" :: "r"(sb + SM_MBPV0 + 8), "r"(1u) : "memory");
    }
    __syncthreads();
    uint32_t tmem;
    asm volatile("ld.shared.b32 %0, [%1];" : "=r"(tmem) : "r"(sb + SM_TMEMPTR));

    // ---- stage Q (all threads): split hi/lo into SW128 K-major tiles ----
    #pragma unroll
    for (int it = 0; it < 16; ++it) {
        int idx = it * THREADS + tid;
        int row = idx >> 5, c4 = idx & 31;
        float4 q = *reinterpret_cast<const float4*>(Qg + (size_t)(q0 + row) * tok + c4 * 4);
        uint32_t h0, l0, h1, l1;
        cvt_pair(q.x, q.y, h0, l0);
        cvt_pair(q.z, q.w, h1, l1);
        int col = c4 * 4;
        uint32_t coff = (uint32_t)((col >> 6) * 16384);
        uint32_t off = SWZ((uint32_t)(row * 128 + (col & 63) * 2));
        *reinterpret_cast<uint2*>(smem + SM_Q_HI + coff + off) = make_uint2(h0, h1);
        *reinterpret_cast<uint2*>(smem + SM_Q_LO + coff + off) = make_uint2(l0, l1);
    }

    // ---- prologue: C-warps convert K(0) -> Kbuf[0] (direct LDG, batched) ----
    if (cw) {
        char* khb = smem + SM_K_HI;      // buf 0
        char* klb = smem + SM_K_LO;
        #pragma unroll
        for (int bb = 0; bb < 2; ++bb) {
            float4 kb[8];
            #pragma unroll
            for (int i = 0; i < 8; ++i) {
                int chunk = (bb * 8 + i) * 128 + ct;
                int row = chunk >> 5, c16 = chunk & 31;
                kb[i] = *reinterpret_cast<const float4*>(Kg + (size_t)row * tok + c16 * 4);
            }
            #pragma unroll
            for (int i = 0; i < 8; ++i) {
                int chunk = (bb * 8 + i) * 128 + ct;
                int row = chunk >> 5, c16 = chunk & 31;
                uint32_t h0, l0, h1, l1;
                cvt_pair(kb[i].x, kb[i].y, h0, l0);
                cvt_pair(kb[i].z, kb[i].w, h1, l1);
                int col = c16 * 4;
                uint32_t coff = (uint32_t)((col >> 6) * 8192);
                uint32_t off = SWZ((uint32_t)(row * 128 + (col & 63) * 2));
                *reinterpret_cast<uint2*>(khb + coff + off) = make_uint2(h0, h1);
                *reinterpret_cast<uint2*>(klb + coff + off) = make_uint2(l0, l1);
            }
        }
        FENCE_ASYNC();
    }
    __syncthreads();

    const uint64_t dQH = desc_k(sb + SM_Q_HI), dQL = desc_k(sb + SM_Q_LO);
    const uint64_t dPH = desc_k(sb + SM_P_HI), dPL = desc_k(sb + SM_P_LO);

    const int m  = (w & 3) * 32 + lane;  // S-warps: my softmax row
    const int qg = q0 + m;
    float lsum = 0.f;

    for (int tt = 0; tt < ntiles; ++tt) {
        const bool more = (tt + 1 < ntiles);

        // top: issue QK(tt) from Kbuf[tt&1] into S[tt&1], commit MBQK[tt&1]
        if (w == 0 && elect1()) {
            uint64_t dKHt = desc_k(sb + SM_K_HI + (tt & 1) * 16384);
            uint64_t dKLt = desc_k(sb + SM_K_LO + (tt & 1) * 16384);
            uint32_t sdst = tmem + S0_COL + (tt & 1) * 64;
            #pragma unroll
            for (int s = 0; s < 8; ++s) {
                uint64_t ao = (uint64_t)((s >> 2) * 1024 + (s & 3) * 2);
                uint64_t bo = (uint64_t)((s >> 2) * 512  + (s & 3) * 2);
                mma_ss(sdst, dQH + ao, dKHt + bo, s > 0 ? 1u : 0u);
            }
            #pragma unroll
            for (int s = 0; s < 8; ++s) {
                uint64_t ao = (uint64_t)((s >> 2) * 1024 + (s & 3) * 2);
                uint64_t bo = (uint64_t)((s >> 2) * 512  + (s & 3) * 2);
                mma_ss(sdst, dQH + ao, dKLt + bo, 1u);
                mma_ss(sdst, dQL + ao, dKHt + bo, 1u);
            }
            TC_COMMIT(sb + SM_MBQK0 + (tt & 1) * 8);
        }

        if (cw) {
            // ---- C-warps: convert K(tt+1) -> Kbuf[(tt+1)&1] ----
            if (more) {
                if (tt >= 1) {  // Kbuf[(tt+1)&1] last read by QK(tt-1) (1 iter old)
                    MBAR_WAIT(sb + SM_MBQK0 + ((tt - 1) & 1) * 8, ((tt - 1) >> 1) & 1);
                }
                const float* Kn = Kg + (size_t)(tt + 1) * BN * tok;
                char* khb = smem + SM_K_HI + ((tt + 1) & 1) * 16384;
                char* klb = smem + SM_K_LO + ((tt + 1) & 1) * 16384;
                #pragma unroll
                for (int bb = 0; bb < 2; ++bb) {
                    float4 kb[8];
                    #pragma unroll
                    for (int i = 0; i < 8; ++i) {
                        int chunk = (bb * 8 + i) * 128 + ct;
                        int row = chunk >> 5, c16 = chunk & 31;
                        kb[i] = *reinterpret_cast<const float4*>(Kn + (size_t)row * tok + c16 * 4);
                    }
                    #pragma unroll
                    for (int i = 0; i < 8; ++i) {
                        int chunk = (bb * 8 + i) * 128 + ct;
                        int row = chunk >> 5, c16 = chunk & 31;
                        uint32_t h0, l0, h1, l1;
                        cvt_pair(kb[i].x, kb[i].y, h0, l0);
                        cvt_pair(kb[i].z, kb[i].w, h1, l1);
                        int col = c16 * 4;
                        uint32_t coff = (uint32_t)((col >> 6) * 8192);
                        uint32_t off = SWZ((uint32_t)(row * 128 + (col & 63) * 2));
                        *reinterpret_cast<uint2*>(khb + coff + off) = make_uint2(h0, h1);
                        *reinterpret_cast<uint2*>(klb + coff + off) = make_uint2(l0, l1);
                    }
                }
            }
            // ---- C slice of V(tt) -> Vbuf[tt&1] ----
            if (tt >= 2) {  // Vbuf[tt&1] last read by PV(tt-2) (2 iters old)
                MBAR_WAIT(sb + SM_MBPV0 + (tt & 1) * 8, ((tt - 2) >> 1) & 1);
            }
            convert_v_slice(Vg + (size_t)tt * BN * tok, tok,
                            smem + SM_V_HI + (tt & 1) * 16384,
                            smem + SM_V_LO + (tt & 1) * 16384, tid);
            FENCE_ASYNC();
        } else {
            // ---- S-warps: softmax(tt-1) + PV(tt-1), then S slice of V(tt) ----
            if (tt > 0) {
                const int kt = tt - 1;
                const int n0 = kt * BN;
                if (tt >= 2) {  // P and Vbuf[tt&1] last read by PV(tt-2)
                    MBAR_WAIT(sb + SM_MBPV0 + (tt & 1) * 8, ((tt - 2) >> 1) & 1);
                }
                MBAR_WAIT(sb + SM_MBQK0 + (kt & 1) * 8, (kt >> 1) & 1);  // QK(kt)
                TC_FENCE_AFTER();
                const bool mk = (kt >= ntiles - 2);
                const uint32_t ssrc = tmem + S0_COL + (kt & 1) * 64;
                uint32_t r0[32], r1[32];
                TC_LD32(r0, ssrc);
                TC_LD32(r1, ssrc + 32);
                TC_WAIT_LD();
                #pragma unroll
                for (int half = 0; half < 2; ++half) {
                    uint32_t* rr = half ? r1 : r0;
                    float pv[32];
                    #pragma unroll
                    for (int j = 0; j < 32; ++j) {
                        float sv = __uint_as_float(rr[j]);
                        float p = ex2(sv * CSC);
                        if (mk && (n0 + half * 32 + j > qg)) p = 0.f;
                        pv[j] = p;
                        lsum += p;
                    }
                    #pragma unroll
                    for (int jp = 0; jp < 16; ++jp) {
                        uint32_t hi, lo;
                        cvt_pair(pv[2 * jp], pv[2 * jp + 1], hi, lo);
                        uint32_t off = SWZ((uint32_t)(m * 128 + (half * 32 + 2 * jp) * 2));
                        *reinterpret_cast<uint32_t*>(smem + SM_P_HI + off) = hi;
                        *reinterpret_cast<uint32_t*>(smem + SM_P_LO + off) = lo;
                    }
                }
                TC_FENCE_BEFORE();
                FENCE_ASYNC();
                SBAR();                           // all P stores visible
                if (w == 0 && elect1()) {
                    #pragma unroll
                    for (int dh = 0; dh < 2; ++dh) {
                        uint64_t dVH = desc_k(sb + SM_V_HI + (kt & 1) * 16384 + dh * 8192);
                        uint64_t dVL = desc_k(sb + SM_V_LO + (kt & 1) * 16384 + dh * 8192);
                        uint32_t dcol = tmem + O_COL + dh * 64;
                        #pragma unroll
                        for (int s = 0; s < 4; ++s) {
                            uint64_t o2 = (uint64_t)(s * 2);
                            mma_ss(dcol, dPH + o2, dVH + o2, (kt > 0 || s > 0) ? 1u : 0u);
                            mma_ss(dcol, dPH + o2, dVL + o2, 1u);
                            mma_ss(dcol, dPL + o2, dVH + o2, 1u);
                        }
                    }
                    TC_COMMIT(sb + SM_MBPV0 + (kt & 1) * 8);
                }
            }
            // ---- S slice of V(tt) -> Vbuf[tt&1]  (guard: MBPV wait above) ----
            convert_v_slice(Vg + (size_t)tt * BN * tok, tok,
                            smem + SM_V_HI + (tt & 1) * 16384,
                            smem + SM_V_LO + (tt & 1) * 16384, tid);
            FENCE_ASYNC();
        }
        __syncthreads();   // joint: Kbuf(tt+1), Vbuf(tt), P, LDTM all settled
    }

    // ---- tail: softmax(ntiles-1) + PV(ntiles-1) ----
    if (!cw) {
        const int kt = ntiles - 1;
        const int n0 = kt * BN;
        MBAR_WAIT(sb + SM_MBPV0 + ((ntiles - 2) & 1) * 8, ((ntiles - 2) >> 1) & 1);
        MBAR_WAIT(sb + SM_MBQK0 + (kt & 1) * 8, (kt >> 1) & 1);
        TC_FENCE_AFTER();
        const uint32_t ssrc = tmem + S0_COL + (kt & 1) * 64;
        uint32_t r0[32], r1[32];
        TC_LD32(r0, ssrc);
        TC_LD32(r1, ssrc + 32);
        TC_WAIT_LD();
        #pragma unroll
        for (int half = 0; half < 2; ++half) {
            uint32_t* rr = half ? r1 : r0;
            float pv[32];
            #pragma unroll
            for (int j = 0; j < 32; ++j) {
                float sv = __uint_as_float(rr[j]);
                float p = ex2(sv * CSC);
                if (n0 + half * 32 + j > qg) p = 0.f;
                pv[j] = p;
                lsum += p;
            }
            #pragma unroll
            for (int jp = 0; jp < 16; ++jp) {
                uint32_t hi, lo;
                cvt_pair(pv[2 * jp], pv[2 * jp + 1], hi, lo);
                uint32_t off = SWZ((uint32_t)(m * 128 + (half * 32 + 2 * jp) * 2));
                *reinterpret_cast<uint32_t*>(smem + SM_P_HI + off) = hi;
                *reinterpret_cast<uint32_t*>(smem + SM_P_LO + off) = lo;
            }
        }
        TC_FENCE_BEFORE();
        FENCE_ASYNC();
        SBAR();
        if (w == 0 && elect1()) {
            #pragma unroll
            for (int dh = 0; dh < 2; ++dh) {
                uint64_t dVH = desc_k(sb + SM_V_HI + (kt & 1) * 16384 + dh * 8192);
                uint64_t dVL = desc_k(sb + SM_V_LO + (kt & 1) * 16384 + dh * 8192);
                uint32_t dcol = tmem + O_COL + dh * 64;
                #pragma unroll
                for (int s = 0; s < 4; ++s) {
                    uint64_t o2 = (uint64_t)(s * 2);
                    mma_ss(dcol, dPH + o2, dVH + o2, 1u);   // kt = ntiles-1 >= 1
                    mma_ss(dcol, dPH + o2, dVL + o2, 1u);
                    mma_ss(dcol, dPL + o2, dVH + o2, 1u);
                }
            }
            TC_COMMIT(sb + SM_MBPV0 + (kt & 1) * 8);
        }
    }

    // ---- epilogue: all warps wait final PV(ntiles-1), normalize, write ----
    MBAR_WAIT(sb + SM_MBPV0 + ((ntiles - 1) & 1) * 8, ((ntiles - 1) >> 1) & 1);
    TC_FENCE_AFTER();
    if (!cw) Ls[m] = lsum;
    __syncthreads();
    {
        const int half_e = w >> 2;
        const int me = (w & 3) * 32 + lane;
        uint32_t r0[32], r1[32];
        TC_LD32(r0, tmem + O_COL + half_e * 64);
        TC_LD32(r1, tmem + O_COL + half_e * 64 + 32);
        TC_WAIT_LD();
        float inv = 1.f / Ls[me];
        float* orow = out + ((size_t)(b * SEQ + q0 + me) * HEADS + h) * DH + half_e * 64;
        #pragma unroll
        for (int j = 0; j < 32; j += 4) {
            float4 a, bq;
            a.x = __uint_as_float(r0[j + 0]) * inv;
            a.y = __uint_as_float(r0[j + 1]) * inv;
            a.z = __uint_as_float(r0[j + 2]) * inv;
            a.w = __uint_as_float(r0[j + 3]) * inv;
            bq.x = __uint_as_float(r1[j + 0]) * inv;
            bq.y = __uint_as_float(r1[j + 1]) * inv;
            bq.z = __uint_as_float(r1[j + 2]) * inv;
            bq.w = __uint_as_float(r1[j + 3]) * inv;
            *reinterpret_cast<float4*>(orow + j) = a;
            *reinterpret_cast<float4*>(orow + 32 + j) = bq;
        }
    }
    __syncthreads();
    if (w == 0) {
        asm volatile("tcgen05.relinquish_alloc_permit.cta_group::1.sync.aligned;");
        asm volatile("tcgen05.dealloc.cta_group::1.sync.aligned.b32 %0, %1;"
                     :: "r"(tmem), "r"((uint32_t)TMEM_NCOLS));
    }

#else
    // ===== SIMT fallback (non-'a' PTX pass only; never selected on GB300) =====
    __syncthreads();
    if (tid < BM) {
        const int row = tid;
        const int qg = q0 + row;
        float acc[DH];
        for (int d = 0; d < DH; ++d) acc[d] = 0.f;
        float lsum = 0.f;
        for (int j = 0; j <= qg; ++j) {
            float s = 0.f;
            for (int d = 0; d < DH; ++d)
                s += Qg[(size_t)qg * tok + d] * Kg[(size_t)j * tok + d];
            float p = ex2(s * CSC);
            lsum += p;
            for (int d = 0; d < DH; ++d)
                acc[d] += p * Vg[(size_t)j * tok + d];
        }
        float inv = 1.f / lsum;
        float* orow = out + ((size_t)(b * SEQ + qg) * HEADS + h) * DH;
        for (int d = 0; d < DH; ++d) orow[d] = acc[d] * inv;
    }
#endif
}

extern "C" void kernel_launch(void* const* d_in, const int* in_sizes, int n_in,
                              void* d_out, int out_size) {
    const float* qkv = (const float*)d_in[0];
    float* out = (float*)d_out;

    cudaFuncSetAttribute(fa_tc_kernel,
                         cudaFuncAttributeMaxDynamicSharedMemorySize, SM_TOTAL);
    dim3 grid(SEQ / BM, HEADS, 2);  // (16, 32, 2)
    fa_tc_kernel<<<grid, THREADS, SM_TOTAL>>>(qkv, out);
}

// round 16
// speedup vs baseline: 1.4394x; 1.4394x over previous
#include <cuda_runtime.h>
#include <cuda_bf16.h>
#include <cstdint>
#include <math.h>

// Causal MHA, qkv packed [B,S,3,H,D] fp32 -> out [B,S,H,D] fp32
// B=2, S=2048, H=32, D=128.
// tcgen05 bf16 SS-mode flash attention, 3-term bf16x2 split (hh+hl+lh).
// R16 = R14 (464us champion) + ONE change: the V^T convert is split by jp
// halves across roles (C-warps jp 0-15, S-warps jp 16-31), with R14's exact
// per-thread d-column mapping (loads scalar coalesced, stores 4-way-conflict
// swizzle pattern) preserved. Balances C/S instruction load (600/300 -> 425/475).

#define SEQ    2048
#define HEADS  32
#define DH     128
#define BM     128
#define BN     64
#define THREADS 256

// smem byte offsets (tiles 1024-aligned for SW128 descriptors)
#define SM_TMEMPTR 0
#define SM_MBQK0   8        // +8 = MBQK1
#define SM_MBPV0   24       // +8 = MBPV1
#define SM_Q_HI    1024                     // 32768
#define SM_Q_LO    (SM_Q_HI + 32768)        // 32768
#define SM_K_HI    (SM_Q_LO + 32768)        // 2 bufs x 16384
#define SM_K_LO    (SM_K_HI + 32768)        // 2 bufs x 16384
#define SM_V_HI    (SM_K_LO + 32768)        // 2 bufs x 16384
#define SM_V_LO    (SM_V_HI + 32768)        // 2 bufs x 16384
#define SM_P_HI    (SM_V_LO + 32768)        // 16384
#define SM_P_LO    (SM_P_HI + 16384)        // 16384
#define SM_LS      (SM_P_LO + 16384)        // 128 fp32
#define SM_TOTAL   (SM_LS + 1024)           // 231424 bytes

// TMEM columns: O fp32 [0:128), S0 [128:192), S1 [192:256)
#define O_COL  0
#define S0_COL 128
#define TMEM_NCOLS 256

// idesc kind::f16: dtype F32@4, atype BF16@7, btype BF16@10, N/8@[17:23), M/16@[24:29)
#define IDESC_64 ((1u<<4)|(1u<<7)|(1u<<10)|(8u<<17)|(8u<<24))   // M=128, N=64

#if defined(__CUDA_ARCH_FEAT_SM103_ALL) || defined(__CUDA_ARCH_FEAT_SM100_ALL) || \
    defined(__CUDA_ARCH_SPECIFIC__) || defined(__CUDA_ARCH_FAMILY_SPECIFIC__)
#define HAS_TCGEN05 1
#else
#define HAS_TCGEN05 0
#endif

static __device__ __forceinline__ uint32_t smem_u32(const void* p) {
    uint32_t a;
    asm("{ .reg .u64 t; cvta.to.shared.u64 t, %1; cvt.u32.u64 %0, t; }" : "=r"(a) : "l"(p));
    return a;
}
static __device__ __forceinline__ float ex2(float x) {
    float y; asm("ex2.approx.ftz.f32 %0, %1;" : "=f"(y) : "f"(x)); return y;
}
static __device__ __forceinline__ void cvt_pair(float e0, float e1, uint32_t& hi, uint32_t& lo) {
    __nv_bfloat162 h = __float22bfloat162_rn(make_float2(e0, e1));
    uint32_t hb = *reinterpret_cast<uint32_t*>(&h);
    float r0 = e0 - __uint_as_float(hb << 16);
    float r1 = e1 - __uint_as_float(hb & 0xFFFF0000u);
    __nv_bfloat162 l = __float22bfloat162_rn(make_float2(r0, r1));
    hi = hb;
    lo = *reinterpret_cast<uint32_t*>(&l);
}
#define SWZ(o) ((o) ^ ((((uint32_t)(o)) >> 3) & 0x70u))

#if HAS_TCGEN05
static __device__ __forceinline__ uint32_t elect1() {
    uint32_t p;
    asm volatile("{\n\t.reg .pred p;\n\telect.sync _|p, 0xFFFFFFFF;\n\tselp.b32 %0,1,0,p;\n\t}" : "=r"(p));
    return p;
}
static __device__ __forceinline__ uint64_t desc_k(uint32_t addr) {
    return ((2ull<<61)|(1ull<<46)|(64ull<<32)|(1ull<<16)) | ((uint64_t)(addr>>4)&0x3FFF);
}
static __device__ __forceinline__ void mma_ss(uint32_t d, uint64_t a, uint64_t b, uint32_t en) {
    asm volatile("{\n\t.reg .pred p;\n\tsetp.ne.u32 p, %4, 0;\n\t"
        "tcgen05.mma.cta_group::1.kind::f16 [%0], %1, %2, %3, {%5,%5,%5,%5}, p;\n\t}"
        :: "r"(d), "l"(a), "l"(b), "r"(IDESC_64), "r"(en), "r"(0u) : "memory");
}
#define TC_LD32(r, addr) \
    asm volatile("tcgen05.ld.sync.aligned.32x32b.x32.b32 " \
        "{%0,%1,%2,%3,%4,%5,%6,%7,%8,%9,%10,%11,%12,%13,%14,%15," \
        "%16,%17,%18,%19,%20,%21,%22,%23,%24,%25,%26,%27,%28,%29,%30,%31}, [%32];" \
        : "=r"((r)[0]),"=r"((r)[1]),"=r"((r)[2]),"=r"((r)[3]),"=r"((r)[4]),"=r"((r)[5]),"=r"((r)[6]),"=r"((r)[7]), \
          "=r"((r)[8]),"=r"((r)[9]),"=r"((r)[10]),"=r"((r)[11]),"=r"((r)[12]),"=r"((r)[13]),"=r"((r)[14]),"=r"((r)[15]), \
          "=r"((r)[16]),"=r"((r)[17]),"=r"((r)[18]),"=r"((r)[19]),"=r"((r)[20]),"=r"((r)[21]),"=r"((r)[22]),"=r"((r)[23]), \
          "=r"((r)[24]),"=r"((r)[25]),"=r"((r)[26]),"=r"((r)[27]),"=r"((r)[28]),"=r"((r)[29]),"=r"((r)[30]),"=r"((r)[31]) \
        : "r"(addr))
#define TC_WAIT_LD() asm volatile("tcgen05.wait::ld.sync.aligned;" ::: "memory")
#define TC_FENCE_AFTER()  asm volatile("tcgen05.fence::after_thread_sync;" ::: "memory")
#define TC_FENCE_BEFORE() asm volatile("tcgen05.fence::before_thread_sync;" ::: "memory")
#define TC_COMMIT(mb) \
    asm volatile("tcgen05.commit.cta_group::1.mbarrier::arrive::one.shared::cluster.b64 [%0];" :: "r"(mb) : "memory")
#define MBAR_WAIT(mb, ph) do { \
    asm volatile("{\n\t.reg .pred P1;\n\t" \
        "WL_%=:\n\t" \
        "mbarrier.try_wait.parity.acquire.cta.shared::cta.b64 P1, [%0], %1, 0x989680;\n\t" \
        "@P1 bra.uni WD_%=;\n\tbra.uni WL_%=;\n\tWD_%=:\n\t}" \
        :: "r"(mb), "r"(ph) : "memory"); \
} while (0)
#define FENCE_ASYNC() asm volatile("fence.proxy.async.shared::cta;" ::: "memory")
#define SBAR() asm volatile("bar.sync 2, 128;" ::: "memory")   // S-warps only

// V^T convert, half jp range, R14 mapping: this thread owns column d,
// converts jp in [jp0, jp0+16). Loads batched (MLP=8), stores swizzled.
static __device__ __forceinline__ void convert_v_half(
    const float* __restrict__ Vt, int tok, char* vhb, char* vlb, int d, int jp0) {
    #pragma unroll
    for (int bb = 0; bb < 2; ++bb) {
        float v0[8], v1[8];
        #pragma unroll
        for (int i = 0; i < 8; ++i) {
            int jp = jp0 + bb * 8 + i;
            v0[i] = Vt[(size_t)(2 * jp) * tok + d];
            v1[i] = Vt[(size_t)(2 * jp + 1) * tok + d];
        }
        #pragma unroll
        for (int i = 0; i < 8; ++i) {
            int jp = jp0 + bb * 8 + i;
            uint32_t hi, lo;
            cvt_pair(v0[i], v1[i], hi, lo);
            uint32_t off = SWZ((uint32_t)(d * 128 + jp * 4));
            *reinterpret_cast<uint32_t*>(vhb + off) = hi;
            *reinterpret_cast<uint32_t*>(vlb + off) = lo;
        }
    }
}
#endif

__global__ __launch_bounds__(THREADS, 1) __cluster_dims__(1, 1, 1)
void fa_tc_kernel(const float* __restrict__ qkv, float* __restrict__ out) {
    const int qt = (int)gridDim.x - 1 - (int)blockIdx.x;  // heavy CTAs first
    const int h = blockIdx.y, b = blockIdx.z;
    const int tid = threadIdx.x, w = tid >> 5, lane = tid & 31;
    const int q0 = qt * BM;
    extern __shared__ char smem[];

    const int HD  = HEADS * DH;
    const int tok = 3 * HD;
    const size_t bhof = (size_t)b * SEQ * tok + (size_t)h * DH;
    const float* Qg = qkv + bhof;
    const float* Kg = qkv + bhof + HD;
    const float* Vg = qkv + bhof + 2 * HD;
    const int ntiles = 2 * (qt + 1);
    const float CSC = 0.12751744f;  // log2(e)/sqrt(128)

#if HAS_TCGEN05
    const uint32_t sb = smem_u32(smem);
    float* Ls = reinterpret_cast<float*>(smem + SM_LS);
    const bool cw = (w >= 4);           // C-warps 4-7
    const int  ct = tid - 128;          // C-thread index 0..127

    if (w == 0) {
        asm volatile("tcgen05.alloc.cta_group::1.sync.aligned.shared::cta.b32 [%0], %1;"
                     :: "r"(sb + SM_TMEMPTR), "r"((uint32_t)TMEM_NCOLS) : "memory");
    }
    if (tid == 0) {
        asm volatile("mbarrier.init.shared.b64 [%0], %1;" :: "r"(sb + SM_MBQK0),     "r"(1u) : "memory");
        asm volatile("mbarrier.init.shared.b64 [%0], %1;" :: "r"(sb + SM_MBQK0 + 8), "r"(1u) : "memory");
        asm volatile("mbarrier.init.shared.b64 [%0], %1;" :: "r"(sb + SM_MBPV0),     "r"(1u) : "memory");
        asm volatile("mbarrier.init.shared.b64 [%0], %1;" :: "r"(sb + SM_MBPV0 + 8), "r"(1u) : "memory");
    }
    __syncthreads();
    uint32_t tmem;
    asm volatile("ld.shared.b32 %0, [%1];" : "=r"(tmem) : "r"(sb + SM_TMEMPTR));

    // ---- stage Q (all threads): split hi/lo into SW128 K-major tiles ----
    #pragma unroll
    for (int it = 0; it < 16; ++it) {
        int idx = it * THREADS + tid;
        int row = idx >> 5, c4 = idx & 31;
        float4 q = *reinterpret_cast<const float4*>(Qg + (size_t)(q0 + row) * tok + c4 * 4);
        uint32_t h0, l0, h1, l1;
        cvt_pair(q.x, q.y, h0, l0);
        cvt_pair(q.z, q.w, h1, l1);
        int col = c4 * 4;
        uint32_t coff = (uint32_t)((col >> 6) * 16384);
        uint32_t off = SWZ((uint32_t)(row * 128 + (col & 63) * 2));
        *reinterpret_cast<uint2*>(smem + SM_Q_HI + coff + off) = make_uint2(h0, h1);
        *reinterpret_cast<uint2*>(smem + SM_Q_LO + coff + off) = make_uint2(l0, l1);
    }

    // ---- prologue: C-warps convert K(0) -> Kbuf[0] (direct LDG, batched) ----
    if (cw) {
        char* khb = smem + SM_K_HI;      // buf 0
        char* klb = smem + SM_K_LO;
        #pragma unroll
        for (int bb = 0; bb < 2; ++bb) {
            float4 kb[8];
            #pragma unroll
            for (int i = 0; i < 8; ++i) {
                int chunk = (bb * 8 + i) * 128 + ct;
                int row = chunk >> 5, c16 = chunk & 31;
                kb[i] = *reinterpret_cast<const float4*>(Kg + (size_t)row * tok + c16 * 4);
            }
            #pragma unroll
            for (int i = 0; i < 8; ++i) {
                int chunk = (bb * 8 + i) * 128 + ct;
                int row = chunk >> 5, c16 = chunk & 31;
                uint32_t h0, l0, h1, l1;
                cvt_pair(kb[i].x, kb[i].y, h0, l0);
                cvt_pair(kb[i].z, kb[i].w, h1, l1);
                int col = c16 * 4;
                uint32_t coff = (uint32_t)((col >> 6) * 8192);
                uint32_t off = SWZ((uint32_t)(row * 128 + (col & 63) * 2));
                *reinterpret_cast<uint2*>(khb + coff + off) = make_uint2(h0, h1);
                *reinterpret_cast<uint2*>(klb + coff + off) = make_uint2(l0, l1);
            }
        }
        FENCE_ASYNC();
    }
    __syncthreads();

    const uint64_t dQH = desc_k(sb + SM_Q_HI), dQL = desc_k(sb + SM_Q_LO);
    const uint64_t dPH = desc_k(sb + SM_P_HI), dPL = desc_k(sb + SM_P_LO);

    const int m  = (w & 3) * 32 + lane;  // S-warps: my softmax row
    const int qg = q0 + m;
    float lsum = 0.f;

    for (int tt = 0; tt < ntiles; ++tt) {
        const bool more = (tt + 1 < ntiles);

        // top: issue QK(tt) from Kbuf[tt&1] into S[tt&1], commit MBQK[tt&1]
        if (w == 0 && elect1()) {
            uint64_t dKHt = desc_k(sb + SM_K_HI + (tt & 1) * 16384);
            uint64_t dKLt = desc_k(sb + SM_K_LO + (tt & 1) * 16384);
            uint32_t sdst = tmem + S0_COL + (tt & 1) * 64;
            #pragma unroll
            for (int s = 0; s < 8; ++s) {
                uint64_t ao = (uint64_t)((s >> 2) * 1024 + (s & 3) * 2);
                uint64_t bo = (uint64_t)((s >> 2) * 512  + (s & 3) * 2);
                mma_ss(sdst, dQH + ao, dKHt + bo, s > 0 ? 1u : 0u);
            }
            #pragma unroll
            for (int s = 0; s < 8; ++s) {
                uint64_t ao = (uint64_t)((s >> 2) * 1024 + (s & 3) * 2);
                uint64_t bo = (uint64_t)((s >> 2) * 512  + (s & 3) * 2);
                mma_ss(sdst, dQH + ao, dKLt + bo, 1u);
                mma_ss(sdst, dQL + ao, dKHt + bo, 1u);
            }
            TC_COMMIT(sb + SM_MBQK0 + (tt & 1) * 8);
        }

        if (cw) {
            // ---- C-warps: convert K(tt+1) -> Kbuf[(tt+1)&1] ----
            if (more) {
                if (tt >= 1) {  // Kbuf[(tt+1)&1] last read by QK(tt-1) (1 iter old)
                    MBAR_WAIT(sb + SM_MBQK0 + ((tt - 1) & 1) * 8, ((tt - 1) >> 1) & 1);
                }
                const float* Kn = Kg + (size_t)(tt + 1) * BN * tok;
                char* khb = smem + SM_K_HI + ((tt + 1) & 1) * 16384;
                char* klb = smem + SM_K_LO + ((tt + 1) & 1) * 16384;
                #pragma unroll
                for (int bb = 0; bb < 2; ++bb) {
                    float4 kb[8];
                    #pragma unroll
                    for (int i = 0; i < 8; ++i) {
                        int chunk = (bb * 8 + i) * 128 + ct;
                        int row = chunk >> 5, c16 = chunk & 31;
                        kb[i] = *reinterpret_cast<const float4*>(Kn + (size_t)row * tok + c16 * 4);
                    }
                    #pragma unroll
                    for (int i = 0; i < 8; ++i) {
                        int chunk = (bb * 8 + i) * 128 + ct;
                        int row = chunk >> 5, c16 = chunk & 31;
                        uint32_t h0, l0, h1, l1;
                        cvt_pair(kb[i].x, kb[i].y, h0, l0);
                        cvt_pair(kb[i].z, kb[i].w, h1, l1);
                        int col = c16 * 4;
                        uint32_t coff = (uint32_t)((col >> 6) * 8192);
                        uint32_t off = SWZ((uint32_t)(row * 128 + (col & 63) * 2));
                        *reinterpret_cast<uint2*>(khb + coff + off) = make_uint2(h0, h1);
                        *reinterpret_cast<uint2*>(klb + coff + off) = make_uint2(l0, l1);
                    }
                }
            }
            // ---- C half of V(tt) (jp 0-15, d = ct) -> Vbuf[tt&1] ----
            if (tt >= 2) {  // Vbuf[tt&1] last read by PV(tt-2) (2 iters old)
                MBAR_WAIT(sb + SM_MBPV0 + (tt & 1) * 8, ((tt - 2) >> 1) & 1);
            }
            convert_v_half(Vg + (size_t)tt * BN * tok, tok,
                           smem + SM_V_HI + (tt & 1) * 16384,
                           smem + SM_V_LO + (tt & 1) * 16384, ct, 0);
            FENCE_ASYNC();
        } else {
            // ---- S-warps: softmax(tt-1) + PV(tt-1), then S half of V(tt) ----
            if (tt > 0) {
                const int kt = tt - 1;
                const int n0 = kt * BN;
                if (tt >= 2) {  // P and Vbuf[tt&1] last read by PV(tt-2)
                    MBAR_WAIT(sb + SM_MBPV0 + (tt & 1) * 8, ((tt - 2) >> 1) & 1);
                }
                MBAR_WAIT(sb + SM_MBQK0 + (kt & 1) * 8, (kt >> 1) & 1);  // QK(kt)
                TC_FENCE_AFTER();
                const bool mk = (kt >= ntiles - 2);
                const uint32_t ssrc = tmem + S0_COL + (kt & 1) * 64;
                uint32_t r0[32], r1[32];
                TC_LD32(r0, ssrc);
                TC_LD32(r1, ssrc + 32);
                TC_WAIT_LD();
                #pragma unroll
                for (int half = 0; half < 2; ++half) {
                    uint32_t* rr = half ? r1 : r0;
                    float pv[32];
                    #pragma unroll
                    for (int j = 0; j < 32; ++j) {
                        float sv = __uint_as_float(rr[j]);
                        float p = ex2(sv * CSC);
                        if (mk && (n0 + half * 32 + j > qg)) p = 0.f;
                        pv[j] = p;
                        lsum += p;
                    }
                    #pragma unroll
                    for (int jp = 0; jp < 16; ++jp) {
                        uint32_t hi, lo;
                        cvt_pair(pv[2 * jp], pv[2 * jp + 1], hi, lo);
                        uint32_t off = SWZ((uint32_t)(m * 128 + (half * 32 + 2 * jp) * 2));
                        *reinterpret_cast<uint32_t*>(smem + SM_P_HI + off) = hi;
                        *reinterpret_cast<uint32_t*>(smem + SM_P_LO + off) = lo;
                    }
                }
                TC_FENCE_BEFORE();
                FENCE_ASYNC();
                SBAR();                           // all P stores visible
                if (w == 0 && elect1()) {
                    #pragma unroll
                    for (int dh = 0; dh < 2; ++dh) {
                        uint64_t dVH = desc_k(sb + SM_V_HI + (kt & 1) * 16384 + dh * 8192);
                        uint64_t dVL = desc_k(sb + SM_V_LO + (kt & 1) * 16384 + dh * 8192);
                        uint32_t dcol = tmem + O_COL + dh * 64;
                        #pragma unroll
                        for (int s = 0; s < 4; ++s) {
                            uint64_t o2 = (uint64_t)(s * 2);
                            mma_ss(dcol, dPH + o2, dVH + o2, (kt > 0 || s > 0) ? 1u : 0u);
                            mma_ss(dcol, dPH + o2, dVL + o2, 1u);
                            mma_ss(dcol, dPL + o2, dVH + o2, 1u);
                        }
                    }
                    TC_COMMIT(sb + SM_MBPV0 + (kt & 1) * 8);
                }
            }
            // ---- S half of V(tt) (jp 16-31, d = tid) -> Vbuf[tt&1] ----
            // Guard: for tt>=2 the MBPV wait above covers Vbuf[tt&1]; tt<2 virgin.
            convert_v_half(Vg + (size_t)tt * BN * tok, tok,
                           smem + SM_V_HI + (tt & 1) * 16384,
                           smem + SM_V_LO + (tt & 1) * 16384, tid, 16);
            FENCE_ASYNC();
        }
        __syncthreads();   // joint: Kbuf(tt+1), Vbuf(tt), P, LDTM all settled
    }

    // ---- tail: softmax(ntiles-1) + PV(ntiles-1) ----
    if (!cw) {
        const int kt = ntiles - 1;
        const int n0 = kt * BN;
        MBAR_WAIT(sb + SM_MBPV0 + ((ntiles - 2) & 1) * 8, ((ntiles - 2) >> 1) & 1);
        MBAR_WAIT(sb + SM_MBQK0 + (kt & 1) * 8, (kt >> 1) & 1);
        TC_FENCE_AFTER();
        const uint32_t ssrc = tmem + S0_COL + (kt & 1) * 64;
        uint32_t r0[32], r1[32];
        TC_LD32(r0, ssrc);
        TC_LD32(r1, ssrc + 32);
        TC_WAIT_LD();
        #pragma unroll
        for (int half = 0; half < 2; ++half) {
            uint32_t* rr = half ? r1 : r0;
            float pv[32];
            #pragma unroll
            for (int j = 0; j < 32; ++j) {
                float sv = __uint_as_float(rr[j]);
                float p = ex2(sv * CSC);
                if (n0 + half * 32 + j > qg) p = 0.f;
                pv[j] = p;
                lsum += p;
            }
            #pragma unroll
            for (int jp = 0; jp < 16; ++jp) {
                uint32_t hi, lo;
                cvt_pair(pv[2 * jp], pv[2 * jp + 1], hi, lo);
                uint32_t off = SWZ((uint32_t)(m * 128 + (half * 32 + 2 * jp) * 2));
                *reinterpret_cast<uint32_t*>(smem + SM_P_HI + off) = hi;
                *reinterpret_cast<uint32_t*>(smem + SM_P_LO + off) = lo;
            }
        }
        TC_FENCE_BEFORE();
        FENCE_ASYNC();
        SBAR();
        if (w == 0 && elect1()) {
            #pragma unroll
            for (int dh = 0; dh < 2; ++dh) {
                uint64_t dVH = desc_k(sb + SM_V_HI + (kt & 1) * 16384 + dh * 8192);
                uint64_t dVL = desc_k(sb + SM_V_LO + (kt & 1) * 16384 + dh * 8192);
                uint32_t dcol = tmem + O_COL + dh * 64;
                #pragma unroll
                for (int s = 0; s < 4; ++s) {
                    uint64_t o2 = (uint64_t)(s * 2);
                    mma_ss(dcol, dPH + o2, dVH + o2, 1u);   // kt = ntiles-1 >= 1
                    mma_ss(dcol, dPH + o2, dVL + o2, 1u);
                    mma_ss(dcol, dPL + o2, dVH + o2, 1u);
                }
            }
            TC_COMMIT(sb + SM_MBPV0 + (kt & 1) * 8);
        }
    }

    // ---- epilogue: all warps wait final PV(ntiles-1), normalize, write ----
    MBAR_WAIT(sb + SM_MBPV0 + ((ntiles - 1) & 1) * 8, ((ntiles - 1) >> 1) & 1);
    TC_FENCE_AFTER();
    if (!cw) Ls[m] = lsum;
    __syncthreads();
    {
        const int half_e = w >> 2;
        const int me = (w & 3) * 32 + lane;
        uint32_t r0[32], r1[32];
        TC_LD32(r0, tmem + O_COL + half_e * 64);
        TC_LD32(r1, tmem + O_COL + half_e * 64 + 32);
        TC_WAIT_LD();
        float inv = 1.f / Ls[me];
        float* orow = out + ((size_t)(b * SEQ + q0 + me) * HEADS + h) * DH + half_e * 64;
        #pragma unroll
        for (int j = 0; j < 32; j += 4) {
            float4 a, bq;
            a.x = __uint_as_float(r0[j + 0]) * inv;
            a.y = __uint_as_float(r0[j + 1]) * inv;
            a.z = __uint_as_float(r0[j + 2]) * inv;
            a.w = __uint_as_float(r0[j + 3]) * inv;
            bq.x = __uint_as_float(r1[j + 0]) * inv;
            bq.y = __uint_as_float(r1[j + 1]) * inv;
            bq.z = __uint_as_float(r1[j + 2]) * inv;
            bq.w = __uint_as_float(r1[j + 3]) * inv;
            *reinterpret_cast<float4*>(orow + j) = a;
            *reinterpret_cast<float4*>(orow + 32 + j) = bq;
        }
    }
    __syncthreads();
    if (w == 0) {
        asm volatile("tcgen05.relinquish_alloc_permit.cta_group::1.sync.aligned;");
        asm volatile("tcgen05.dealloc.cta_group::1.sync.aligned.b32 %0, %1;"
                     :: "r"(tmem), "r"((uint32_t)TMEM_NCOLS));
    }

#else
    // ===== SIMT fallback (non-'a' PTX pass only; never selected on GB300) =====
    __syncthreads();
    if (tid < BM) {
        const int row = tid;
        const int qg = q0 + row;
        float acc[DH];
        for (int d = 0; d < DH; ++d) acc[d] = 0.f;
        float lsum = 0.f;
        for (int j = 0; j <= qg; ++j) {
            float s = 0.f;
            for (int d = 0; d < DH; ++d)
                s += Qg[(size_t)qg * tok + d] * Kg[(size_t)j * tok + d];
            float p = ex2(s * CSC);
            lsum += p;
            for (int d = 0; d < DH; ++d)
                acc[d] += p * Vg[(size_t)j * tok + d];
        }
        float inv = 1.f / lsum;
        float* orow = out + ((size_t)(b * SEQ + qg) * HEADS + h) * DH;
        for (int d = 0; d < DH; ++d) orow[d] = acc[d] * inv;
    }
#endif
}

extern "C" void kernel_launch(void* const* d_in, const int* in_sizes, int n_in,
                              void* d_out, int out_size) {
    const float* qkv = (const float*)d_in[0];
    float* out = (float*)d_out;

    cudaFuncSetAttribute(fa_tc_kernel,
                         cudaFuncAttributeMaxDynamicSharedMemorySize, SM_TOTAL);
    dim3 grid(SEQ / BM, HEADS, 2);  // (16, 32, 2)
    fa_tc_kernel<<<grid, THREADS, SM_TOTAL>>>(qkv, out);
}

// round 17
// speedup vs baseline: 1.6532x; 1.1486x over previous
#include <cuda_runtime.h>
#include <cuda_bf16.h>
#include <cstdint>
#include <math.h>

// Causal MHA, qkv packed [B,S,3,H,D] fp32 -> out [B,S,H,D] fp32
// B=2, S=2048, H=32, D=128.
// tcgen05 bf16 SS-mode flash attention, 3-term bf16x2 split (hh+hl+lh).
// R17 = R16 (455us) + three stall-structure changes:
//   (1) joint barrier is now one-sided: C-warps bar.arrive, S-warps bar.sync
//       (two alternating named barriers by tile parity -> lap-proof). C-warps
//       never wait for softmax; their mbar waits alone gate buffer reuse.
//   (2) S-warps' V-half LDGs hoisted above waits+softmax (latency hidden).
//   (3) PV uses N=128 MMAs (12 issues instead of 24).

#define SEQ    2048
#define HEADS  32
#define DH     128
#define BM     128
#define BN     64
#define THREADS 256

// smem byte offsets (tiles 1024-aligned for SW128 descriptors)
#define SM_TMEMPTR 0
#define SM_MBQK0   8        // +8 = MBQK1
#define SM_MBPV0   24       // +8 = MBPV1
#define SM_Q_HI    1024                     // 32768
#define SM_Q_LO    (SM_Q_HI + 32768)        // 32768
#define SM_K_HI    (SM_Q_LO + 32768)        // 2 bufs x 16384
#define SM_K_LO    (SM_K_HI + 32768)        // 2 bufs x 16384
#define SM_V_HI    (SM_K_LO + 32768)        // 2 bufs x 16384
#define SM_V_LO    (SM_V_HI + 32768)        // 2 bufs x 16384
#define SM_P_HI    (SM_V_LO + 32768)        // 16384
#define SM_P_LO    (SM_P_HI + 16384)        // 16384
#define SM_LS      (SM_P_LO + 16384)        // 128 fp32
#define SM_TOTAL   (SM_LS + 1024)           // 231424 bytes

// TMEM columns: O fp32 [0:128), S0 [128:192), S1 [192:256)
#define O_COL  0
#define S0_COL 128
#define TMEM_NCOLS 256

// idesc kind::f16: dtype F32@4, atype BF16@7, btype BF16@10, N/8@[17:23), M/16@[24:29)
#define IDESC_64  ((1u<<4)|(1u<<7)|(1u<<10)|(8u<<17)|(8u<<24))    // M=128, N=64
#define IDESC_128 ((1u<<4)|(1u<<7)|(1u<<10)|(16u<<17)|(8u<<24))   // M=128, N=128

#if defined(__CUDA_ARCH_FEAT_SM103_ALL) || defined(__CUDA_ARCH_FEAT_SM100_ALL) || \
    defined(__CUDA_ARCH_SPECIFIC__) || defined(__CUDA_ARCH_FAMILY_SPECIFIC__)
#define HAS_TCGEN05 1
#else
#define HAS_TCGEN05 0
#endif

static __device__ __forceinline__ uint32_t smem_u32(const void* p) {
    uint32_t a;
    asm("{ .reg .u64 t; cvta.to.shared.u64 t, %1; cvt.u32.u64 %0, t; }" : "=r"(a) : "l"(p));
    return a;
}
static __device__ __forceinline__ float ex2(float x) {
    float y; asm("ex2.approx.ftz.f32 %0, %1;" : "=f"(y) : "f"(x)); return y;
}
static __device__ __forceinline__ void cvt_pair(float e0, float e1, uint32_t& hi, uint32_t& lo) {
    __nv_bfloat162 h = __float22bfloat162_rn(make_float2(e0, e1));
    uint32_t hb = *reinterpret_cast<uint32_t*>(&h);
    float r0 = e0 - __uint_as_float(hb << 16);
    float r1 = e1 - __uint_as_float(hb & 0xFFFF0000u);
    __nv_bfloat162 l = __float22bfloat162_rn(make_float2(r0, r1));
    hi = hb;
    lo = *reinterpret_cast<uint32_t*>(&l);
}
#define SWZ(o) ((o) ^ ((((uint32_t)(o)) >> 3) & 0x70u))

#if HAS_TCGEN05
static __device__ __forceinline__ uint32_t elect1() {
    uint32_t p;
    asm volatile("{\n\t.reg .pred p;\n\telect.sync _|p, 0xFFFFFFFF;\n\tselp.b32 %0,1,0,p;\n\t}" : "=r"(p));
    return p;
}
static __device__ __forceinline__ uint64_t desc_k(uint32_t addr) {
    return ((2ull<<61)|(1ull<<46)|(64ull<<32)|(1ull<<16)) | ((uint64_t)(addr>>4)&0x3FFF);
}
static __device__ __forceinline__ void mma_ss(uint32_t d, uint64_t a, uint64_t b, uint32_t id, uint32_t en) {
    asm volatile("{\n\t.reg .pred p;\n\tsetp.ne.u32 p, %4, 0;\n\t"
        "tcgen05.mma.cta_group::1.kind::f16 [%0], %1, %2, %3, {%5,%5,%5,%5}, p;\n\t}"
        :: "r"(d), "l"(a), "l"(b), "r"(id), "r"(en), "r"(0u) : "memory");
}
#define TC_LD32(r, addr) \
    asm volatile("tcgen05.ld.sync.aligned.32x32b.x32.b32 " \
        "{%0,%1,%2,%3,%4,%5,%6,%7,%8,%9,%10,%11,%12,%13,%14,%15," \
        "%16,%17,%18,%19,%20,%21,%22,%23,%24,%25,%26,%27,%28,%29,%30,%31}, [%32];" \
        : "=r"((r)[0]),"=r"((r)[1]),"=r"((r)[2]),"=r"((r)[3]),"=r"((r)[4]),"=r"((r)[5]),"=r"((r)[6]),"=r"((r)[7]), \
          "=r"((r)[8]),"=r"((r)[9]),"=r"((r)[10]),"=r"((r)[11]),"=r"((r)[12]),"=r"((r)[13]),"=r"((r)[14]),"=r"((r)[15]), \
          "=r"((r)[16]),"=r"((r)[17]),"=r"((r)[18]),"=r"((r)[19]),"=r"((r)[20]),"=r"((r)[21]),"=r"((r)[22]),"=r"((r)[23]), \
          "=r"((r)[24]),"=r"((r)[25]),"=r"((r)[26]),"=r"((r)[27]),"=r"((r)[28]),"=r"((r)[29]),"=r"((r)[30]),"=r"((r)[31]) \
        : "r"(addr))
#define TC_WAIT_LD() asm volatile("tcgen05.wait::ld.sync.aligned;" ::: "memory")
#define TC_FENCE_AFTER()  asm volatile("tcgen05.fence::after_thread_sync;" ::: "memory")
#define TC_FENCE_BEFORE() asm volatile("tcgen05.fence::before_thread_sync;" ::: "memory")
#define TC_COMMIT(mb) \
    asm volatile("tcgen05.commit.cta_group::1.mbarrier::arrive::one.shared::cluster.b64 [%0];" :: "r"(mb) : "memory")
#define MBAR_WAIT(mb, ph) do { \
    asm volatile("{\n\t.reg .pred P1;\n\t" \
        "WL_%=:\n\t" \
        "mbarrier.try_wait.parity.acquire.cta.shared::cta.b64 P1, [%0], %1, 0x989680;\n\t" \
        "@P1 bra.uni WD_%=;\n\tbra.uni WL_%=;\n\tWD_%=:\n\t}" \
        :: "r"(mb), "r"(ph) : "memory"); \
} while (0)
#define FENCE_ASYNC() asm volatile("fence.proxy.async.shared::cta;" ::: "memory")
#define SBAR() asm volatile("bar.sync 2, 128;" ::: "memory")   // S-warps only
#define JBAR_SYNC(id)   asm volatile("bar.sync %0, 256;"   :: "r"(id) : "memory")
#define JBAR_ARRIVE(id) asm volatile("bar.arrive %0, 256;" :: "r"(id) : "memory")

// V^T convert, half jp range (C-path, internal loads): thread owns column d,
// converts jp in [0,16). Loads batched (MLP=8), stores swizzled.
static __device__ __forceinline__ void convert_v_half_c(
    const float* __restrict__ Vt, int tok, char* vhb, char* vlb, int d) {
    #pragma unroll
    for (int bb = 0; bb < 2; ++bb) {
        float v0[8], v1[8];
        #pragma unroll
        for (int i = 0; i < 8; ++i) {
            int jp = bb * 8 + i;
            v0[i] = Vt[(size_t)(2 * jp) * tok + d];
            v1[i] = Vt[(size_t)(2 * jp + 1) * tok + d];
        }
        #pragma unroll
        for (int i = 0; i < 8; ++i) {
            int jp = bb * 8 + i;
            uint32_t hi, lo;
            cvt_pair(v0[i], v1[i], hi, lo);
            uint32_t off = SWZ((uint32_t)(d * 128 + jp * 4));
            *reinterpret_cast<uint32_t*>(vhb + off) = hi;
            *reinterpret_cast<uint32_t*>(vlb + off) = lo;
        }
    }
}
#endif

__global__ __launch_bounds__(THREADS, 1) __cluster_dims__(1, 1, 1)
void fa_tc_kernel(const float* __restrict__ qkv, float* __restrict__ out) {
    const int qt = (int)gridDim.x - 1 - (int)blockIdx.x;  // heavy CTAs first
    const int h = blockIdx.y, b = blockIdx.z;
    const int tid = threadIdx.x, w = tid >> 5, lane = tid & 31;
    const int q0 = qt * BM;
    extern __shared__ char smem[];

    const int HD  = HEADS * DH;
    const int tok = 3 * HD;
    const size_t bhof = (size_t)b * SEQ * tok + (size_t)h * DH;
    const float* Qg = qkv + bhof;
    const float* Kg = qkv + bhof + HD;
    const float* Vg = qkv + bhof + 2 * HD;
    const int ntiles = 2 * (qt + 1);
    const float CSC = 0.12751744f;  // log2(e)/sqrt(128)

#if HAS_TCGEN05
    const uint32_t sb = smem_u32(smem);
    float* Ls = reinterpret_cast<float*>(smem + SM_LS);
    const bool cw = (w >= 4);           // C-warps 4-7
    const int  ct = tid - 128;          // C-thread index 0..127

    if (w == 0) {
        asm volatile("tcgen05.alloc.cta_group::1.sync.aligned.shared::cta.b32 [%0], %1;"
                     :: "r"(sb + SM_TMEMPTR), "r"((uint32_t)TMEM_NCOLS) : "memory");
    }
    if (tid == 0) {
        asm volatile("mbarrier.init.shared.b64 [%0], %1;" :: "r"(sb + SM_MBQK0),     "r"(1u) : "memory");
        asm volatile("mbarrier.init.shared.b64 [%0], %1;" :: "r"(sb + SM_MBQK0 + 8), "r"(1u) : "memory");
        asm volatile("mbarrier.init.shared.b64 [%0], %1;" :: "r"(sb + SM_MBPV0),     "r"(1u) : "memory");
        asm volatile("mbarrier.init.shared.b64 [%0], %1;" :: "r"(sb + SM_MBPV0 + 8), "r"(1u) : "memory");
    }
    __syncthreads();
    uint32_t tmem;
    asm volatile("ld.shared.b32 %0, [%1];" : "=r"(tmem) : "r"(sb + SM_TMEMPTR));

    // ---- stage Q (all threads): split hi/lo into SW128 K-major tiles ----
    #pragma unroll
    for (int it = 0; it < 16; ++it) {
        int idx = it * THREADS + tid;
        int row = idx >> 5, c4 = idx & 31;
        float4 q = *reinterpret_cast<const float4*>(Qg + (size_t)(q0 + row) * tok + c4 * 4);
        uint32_t h0, l0, h1, l1;
        cvt_pair(q.x, q.y, h0, l0);
        cvt_pair(q.z, q.w, h1, l1);
        int col = c4 * 4;
        uint32_t coff = (uint32_t)((col >> 6) * 16384);
        uint32_t off = SWZ((uint32_t)(row * 128 + (col & 63) * 2));
        *reinterpret_cast<uint2*>(smem + SM_Q_HI + coff + off) = make_uint2(h0, h1);
        *reinterpret_cast<uint2*>(smem + SM_Q_LO + coff + off) = make_uint2(l0, l1);
    }

    // ---- prologue: C-warps convert K(0) -> Kbuf[0] (direct LDG, batched) ----
    if (cw) {
        char* khb = smem + SM_K_HI;      // buf 0
        char* klb = smem + SM_K_LO;
        #pragma unroll
        for (int bb = 0; bb < 2; ++bb) {
            float4 kb[8];
            #pragma unroll
            for (int i = 0; i < 8; ++i) {
                int chunk = (bb * 8 + i) * 128 + ct;
                int row = chunk >> 5, c16 = chunk & 31;
                kb[i] = *reinterpret_cast<const float4*>(Kg + (size_t)row * tok + c16 * 4);
            }
            #pragma unroll
            for (int i = 0; i < 8; ++i) {
                int chunk = (bb * 8 + i) * 128 + ct;
                int row = chunk >> 5, c16 = chunk & 31;
                uint32_t h0, l0, h1, l1;
                cvt_pair(kb[i].x, kb[i].y, h0, l0);
                cvt_pair(kb[i].z, kb[i].w, h1, l1);
                int col = c16 * 4;
                uint32_t coff = (uint32_t)((col >> 6) * 8192);
                uint32_t off = SWZ((uint32_t)(row * 128 + (col & 63) * 2));
                *reinterpret_cast<uint2*>(khb + coff + off) = make_uint2(h0, h1);
                *reinterpret_cast<uint2*>(klb + coff + off) = make_uint2(l0, l1);
            }
        }
        FENCE_ASYNC();
    }
    __syncthreads();

    const uint64_t dQH = desc_k(sb + SM_Q_HI), dQL = desc_k(sb + SM_Q_LO);
    const uint64_t dPH = desc_k(sb + SM_P_HI), dPL = desc_k(sb + SM_P_LO);

    const int m  = (w & 3) * 32 + lane;  // S-warps: my softmax row
    const int qg = q0 + m;
    float lsum = 0.f;

    for (int tt = 0; tt < ntiles; ++tt) {
        const bool more = (tt + 1 < ntiles);

        // top: issue QK(tt) from Kbuf[tt&1] into S[tt&1], commit MBQK[tt&1]
        if (w == 0 && elect1()) {
            uint64_t dKHt = desc_k(sb + SM_K_HI + (tt & 1) * 16384);
            uint64_t dKLt = desc_k(sb + SM_K_LO + (tt & 1) * 16384);
            uint32_t sdst = tmem + S0_COL + (tt & 1) * 64;
            #pragma unroll
            for (int s = 0; s < 8; ++s) {
                uint64_t ao = (uint64_t)((s >> 2) * 1024 + (s & 3) * 2);
                uint64_t bo = (uint64_t)((s >> 2) * 512  + (s & 3) * 2);
                mma_ss(sdst, dQH + ao, dKHt + bo, IDESC_64, s > 0 ? 1u : 0u);
            }
            #pragma unroll
            for (int s = 0; s < 8; ++s) {
                uint64_t ao = (uint64_t)((s >> 2) * 1024 + (s & 3) * 2);
                uint64_t bo = (uint64_t)((s >> 2) * 512  + (s & 3) * 2);
                mma_ss(sdst, dQH + ao, dKLt + bo, IDESC_64, 1u);
                mma_ss(sdst, dQL + ao, dKHt + bo, IDESC_64, 1u);
            }
            TC_COMMIT(sb + SM_MBQK0 + (tt & 1) * 8);
        }

        if (cw) {
            // ---- C-warps: convert K(tt+1) -> Kbuf[(tt+1)&1] ----
            if (more) {
                if (tt >= 1) {  // Kbuf[(tt+1)&1] last read by QK(tt-1)
                    MBAR_WAIT(sb + SM_MBQK0 + ((tt - 1) & 1) * 8, ((tt - 1) >> 1) & 1);
                }
                const float* Kn = Kg + (size_t)(tt + 1) * BN * tok;
                char* khb = smem + SM_K_HI + ((tt + 1) & 1) * 16384;
                char* klb = smem + SM_K_LO + ((tt + 1) & 1) * 16384;
                #pragma unroll
                for (int bb = 0; bb < 2; ++bb) {
                    float4 kb[8];
                    #pragma unroll
                    for (int i = 0; i < 8; ++i) {
                        int chunk = (bb * 8 + i) * 128 + ct;
                        int row = chunk >> 5, c16 = chunk & 31;
                        kb[i] = *reinterpret_cast<const float4*>(Kn + (size_t)row * tok + c16 * 4);
                    }
                    #pragma unroll
                    for (int i = 0; i < 8; ++i) {
                        int chunk = (bb * 8 + i) * 128 + ct;
                        int row = chunk >> 5, c16 = chunk & 31;
                        uint32_t h0, l0, h1, l1;
                        cvt_pair(kb[i].x, kb[i].y, h0, l0);
                        cvt_pair(kb[i].z, kb[i].w, h1, l1);
                        int col = c16 * 4;
                        uint32_t coff = (uint32_t)((col >> 6) * 8192);
                        uint32_t off = SWZ((uint32_t)(row * 128 + (col & 63) * 2));
                        *reinterpret_cast<uint2*>(khb + coff + off) = make_uint2(h0, h1);
                        *reinterpret_cast<uint2*>(klb + coff + off) = make_uint2(l0, l1);
                    }
                }
            }
            // ---- C half of V(tt) (jp 0-15, d = ct) -> Vbuf[tt&1] ----
            if (tt >= 2) {  // Vbuf[tt&1] last read by PV(tt-2)
                MBAR_WAIT(sb + SM_MBPV0 + (tt & 1) * 8, ((tt - 2) >> 1) & 1);
            }
            convert_v_half_c(Vg + (size_t)tt * BN * tok, tok,
                             smem + SM_V_HI + (tt & 1) * 16384,
                             smem + SM_V_LO + (tt & 1) * 16384, ct);
            FENCE_ASYNC();
        } else {
            // ---- S-warps: hoist V-half loads (jp 16-31, d = tid) ----
            const float* Vt = Vg + (size_t)tt * BN * tok;
            float v0[16], v1[16];
            #pragma unroll
            for (int i = 0; i < 16; ++i) {
                int jp = 16 + i;
                v0[i] = Vt[(size_t)(2 * jp) * tok + tid];
                v1[i] = Vt[(size_t)(2 * jp + 1) * tok + tid];
            }
            // ---- softmax(tt-1) + PV(tt-1) ----
            if (tt > 0) {
                const int kt = tt - 1;
                const int n0 = kt * BN;
                if (tt >= 2) {  // P and Vbuf[tt&1] last read by PV(tt-2)
                    MBAR_WAIT(sb + SM_MBPV0 + (tt & 1) * 8, ((tt - 2) >> 1) & 1);
                }
                MBAR_WAIT(sb + SM_MBQK0 + (kt & 1) * 8, (kt >> 1) & 1);  // QK(kt)
                TC_FENCE_AFTER();
                const bool mk = (kt >= ntiles - 2);
                const uint32_t ssrc = tmem + S0_COL + (kt & 1) * 64;
                uint32_t r0[32], r1[32];
                TC_LD32(r0, ssrc);
                TC_LD32(r1, ssrc + 32);
                TC_WAIT_LD();
                #pragma unroll
                for (int half = 0; half < 2; ++half) {
                    uint32_t* rr = half ? r1 : r0;
                    #pragma unroll
                    for (int jp = 0; jp < 16; ++jp) {
                        float p0 = ex2(__uint_as_float(rr[2 * jp]) * CSC);
                        float p1 = ex2(__uint_as_float(rr[2 * jp + 1]) * CSC);
                        if (mk) {
                            int nc = n0 + half * 32 + 2 * jp;
                            if (nc     > qg) p0 = 0.f;
                            if (nc + 1 > qg) p1 = 0.f;
                        }
                        lsum += p0 + p1;
                        uint32_t hi, lo;
                        cvt_pair(p0, p1, hi, lo);
                        uint32_t off = SWZ((uint32_t)(m * 128 + (half * 32 + 2 * jp) * 2));
                        *reinterpret_cast<uint32_t*>(smem + SM_P_HI + off) = hi;
                        *reinterpret_cast<uint32_t*>(smem + SM_P_LO + off) = lo;
                    }
                }
                TC_FENCE_BEFORE();
                FENCE_ASYNC();
                SBAR();                           // all P stores visible
                if (w == 0 && elect1()) {
                    uint64_t dVH = desc_k(sb + SM_V_HI + (kt & 1) * 16384);
                    uint64_t dVL = desc_k(sb + SM_V_LO + (kt & 1) * 16384);
                    #pragma unroll
                    for (int s = 0; s < 4; ++s) {
                        uint64_t o2 = (uint64_t)(s * 2);
                        mma_ss(tmem + O_COL, dPH + o2, dVH + o2, IDESC_128, (kt > 0 || s > 0) ? 1u : 0u);
                        mma_ss(tmem + O_COL, dPH + o2, dVL + o2, IDESC_128, 1u);
                        mma_ss(tmem + O_COL, dPL + o2, dVH + o2, IDESC_128, 1u);
                    }
                    TC_COMMIT(sb + SM_MBPV0 + (kt & 1) * 8);
                }
            }
            // ---- convert + store the hoisted V half ----
            {
                char* vhb = smem + SM_V_HI + (tt & 1) * 16384;
                char* vlb = smem + SM_V_LO + (tt & 1) * 16384;
                #pragma unroll
                for (int i = 0; i < 16; ++i) {
                    int jp = 16 + i;
                    uint32_t hi, lo;
                    cvt_pair(v0[i], v1[i], hi, lo);
                    uint32_t off = SWZ((uint32_t)(tid * 128 + jp * 4));
                    *reinterpret_cast<uint32_t*>(vhb + off) = hi;
                    *reinterpret_cast<uint32_t*>(vlb + off) = lo;
                }
            }
            FENCE_ASYNC();
        }
        // one-sided joint barrier (alternating ids -> lap-proof)
        if (cw) { JBAR_ARRIVE(3 + (tt & 1)); }
        else    { JBAR_SYNC(3 + (tt & 1)); }
    }

    // ---- tail: softmax(ntiles-1) + PV(ntiles-1) (S-warps only) ----
    if (!cw) {
        const int kt = ntiles - 1;
        const int n0 = kt * BN;
        MBAR_WAIT(sb + SM_MBPV0 + ((ntiles - 2) & 1) * 8, ((ntiles - 2) >> 1) & 1);
        MBAR_WAIT(sb + SM_MBQK0 + (kt & 1) * 8, (kt >> 1) & 1);
        TC_FENCE_AFTER();
        const uint32_t ssrc = tmem + S0_COL + (kt & 1) * 64;
        uint32_t r0[32], r1[32];
        TC_LD32(r0, ssrc);
        TC_LD32(r1, ssrc + 32);
        TC_WAIT_LD();
        #pragma unroll
        for (int half = 0; half < 2; ++half) {
            uint32_t* rr = half ? r1 : r0;
            #pragma unroll
            for (int jp = 0; jp < 16; ++jp) {
                float p0 = ex2(__uint_as_float(rr[2 * jp]) * CSC);
                float p1 = ex2(__uint_as_float(rr[2 * jp + 1]) * CSC);
                int nc = n0 + half * 32 + 2 * jp;
                if (nc     > qg) p0 = 0.f;
                if (nc + 1 > qg) p1 = 0.f;
                lsum += p0 + p1;
                uint32_t hi, lo;
                cvt_pair(p0, p1, hi, lo);
                uint32_t off = SWZ((uint32_t)(m * 128 + (half * 32 + 2 * jp) * 2));
                *reinterpret_cast<uint32_t*>(smem + SM_P_HI + off) = hi;
                *reinterpret_cast<uint32_t*>(smem + SM_P_LO + off) = lo;
            }
        }
        TC_FENCE_BEFORE();
        FENCE_ASYNC();
        SBAR();
        if (w == 0 && elect1()) {
            uint64_t dVH = desc_k(sb + SM_V_HI + (kt & 1) * 16384);
            uint64_t dVL = desc_k(sb + SM_V_LO + (kt & 1) * 16384);
            #pragma unroll
            for (int s = 0; s < 4; ++s) {
                uint64_t o2 = (uint64_t)(s * 2);
                mma_ss(tmem + O_COL, dPH + o2, dVH + o2, IDESC_128, 1u);  // kt >= 1
                mma_ss(tmem + O_COL, dPH + o2, dVL + o2, IDESC_128, 1u);
                mma_ss(tmem + O_COL, dPL + o2, dVH + o2, IDESC_128, 1u);
            }
            TC_COMMIT(sb + SM_MBPV0 + (kt & 1) * 8);
        }
    }

    // ---- epilogue: all warps wait final PV(ntiles-1), normalize, write ----
    MBAR_WAIT(sb + SM_MBPV0 + ((ntiles - 1) & 1) * 8, ((ntiles - 1) >> 1) & 1);
    TC_FENCE_AFTER();
    if (!cw) Ls[m] = lsum;
    __syncthreads();
    {
        const int half_e = w >> 2;
        const int me = (w & 3) * 32 + lane;
        uint32_t r0[32], r1[32];
        TC_LD32(r0, tmem + O_COL + half_e * 64);
        TC_LD32(r1, tmem + O_COL + half_e * 64 + 32);
        TC_WAIT_LD();
        float inv = 1.f / Ls[me];
        float* orow = out + ((size_t)(b * SEQ + q0 + me) * HEADS + h) * DH + half_e * 64;
        #pragma unroll
        for (int j = 0; j < 32; j += 4) {
            float4 a, bq;
            a.x = __uint_as_float(r0[j + 0]) * inv;
            a.y = __uint_as_float(r0[j + 1]) * inv;
            a.z = __uint_as_float(r0[j + 2]) * inv;
            a.w = __uint_as_float(r0[j + 3]) * inv;
            bq.x = __uint_as_float(r1[j + 0]) * inv;
            bq.y = __uint_as_float(r1[j + 1]) * inv;
            bq.z = __uint_as_float(r1[j + 2]) * inv;
            bq.w = __uint_as_float(r1[j + 3]) * inv;
            *reinterpret_cast<float4*>(orow + j) = a;
            *reinterpret_cast<float4*>(orow + 32 + j) = bq;
        }
    }
    __syncthreads();
    if (w == 0) {
        asm volatile("tcgen05.relinquish_alloc_permit.cta_group::1.sync.aligned;");
        asm volatile("tcgen05.dealloc.cta_group::1.sync.aligned.b32 %0, %1;"
                     :: "r"(tmem), "r"((uint32_t)TMEM_NCOLS));
    }

#else
    // ===== SIMT fallback (non-'a' PTX pass only; never selected on GB300) =====
    __syncthreads();
    if (tid < BM) {
        const int row = tid;
        const int qg = q0 + row;
        float acc[DH];
        for (int d = 0; d < DH; ++d) acc[d] = 0.f;
        float lsum = 0.f;
        for (int j = 0; j <= qg; ++j) {
            float s = 0.f;
            for (int d = 0; d < DH; ++d)
                s += Qg[(size_t)qg * tok + d] * Kg[(size_t)j * tok + d];
            float p = ex2(s * CSC);
            lsum += p;
            for (int d = 0; d < DH; ++d)
                acc[d] += p * Vg[(size_t)j * tok + d];
        }
        float inv = 1.f / lsum;
        float* orow = out + ((size_t)(b * SEQ + qg) * HEADS + h) * DH;
        for (int d = 0; d < DH; ++d) orow[d] = acc[d] * inv;
    }
#endif
}

extern "C" void kernel_launch(void* const* d_in, const int* in_sizes, int n_in,
                              void* d_out, int out_size) {
    const float* qkv = (const float*)d_in[0];
    float* out = (float*)d_out;

    cudaFuncSetAttribute(fa_tc_kernel,
                         cudaFuncAttributeMaxDynamicSharedMemorySize, SM_TOTAL);
    dim3 grid(SEQ / BM, HEADS, 2);  // (16, 32, 2)
    fa_tc_kernel<<<grid, THREADS, SM_TOTAL>>>(qkv, out);
}